// round 4
// baseline (speedup 1.0000x reference)
#include <cuda_runtime.h>
#include <cuda_bf16.h>
#include <cstddef>

// Problem constants: B=32, H=W=64, C=64, K=3, S=1, PAD=1
// Hp=Wp=66, OUT=192.  Pure gather:
//   out[b,c2,r,s] = up_flat[c2*4356 + ip*66 + jp],  ip=r/3+r%3, jp=s/3+s%3
//   up_flat[t]: p=t>>6, c=t&63, rp=p/66, cp=p%66;
//   interior(rp,cp) -> in[b, (p-2rp-65), c] else 0.
// Key: s=3m..3m+2 maps to src[m..m+2] (contiguous), so 12 outputs
// (s=12q..12q+11) need only src[4q..4q+5].
#define HP      66
#define HPP     68               // padded row stride (multiple of 4 for LDS.128)
#define NP      (HP * HP)        // 4356
#define OUT     192
#define BATCH   32

__global__ __launch_bounds__(192)
void padding_jacobians_kernel(const float* __restrict__ in,
                              float* __restrict__ out) {
    __shared__ float sm[HP * HPP];         // 66*68*4 = 17952 B

    const unsigned c2 = blockIdx.x;        // 0..63
    const unsigned b  = blockIdx.y;        // 0..31
    const int tid = threadIdx.x;           // 0..191

    const float* __restrict__ inb = in + (size_t)b * (64 * 64 * 64);
    const unsigned base_t = c2 * NP;       // multiple of 4

    // ---- Load phase: padded window, float2 granularity (t even => c even,
    // never crosses a p boundary since 2 | 64). 4356/2 = 2178 float2s.
    #pragma unroll 1
    for (unsigned idx = tid; idx < NP / 2; idx += 192) {
        unsigned i   = 2u * idx;                 // offset within window (even)
        unsigned row = (i * 993u) >> 16;         // == i/66 for i < 4356 (exact)
        unsigned col = i - 66u * row;
        unsigned t   = base_t + i;
        unsigned p   = t >> 6;
        unsigned c   = t & 63u;
        unsigned rp  = (p * 993u) >> 16;         // == p/66 for p < 4356
        unsigned cp  = p - 66u * rp;
        float2 v = make_float2(0.f, 0.f);
        if ((rp - 1u) < 64u && (cp - 1u) < 64u) {
            v = *reinterpret_cast<const float2*>(inb + ((p - 2u * rp - 65u) << 6) + c);
        }
        *reinterpret_cast<float2*>(sm + row * HPP + col) = v;   // aligned: even
    }
    __syncthreads();

    // ---- Store phase: 16 threads per output row, 12 rows in flight.
    // Thread (q, ty) writes out[r][12q .. 12q+11] from src[4q .. 4q+5]:
    //   [a0,a1,a2, a1,a2,a3, a2,a3,a4, a3,a4,a5]
    const int q  = tid & 15;                 // 0..15
    const int ty = tid >> 4;                 // 0..11
    int ip = ty / 3 + ty % 3;                // ip(r=ty); r stride 12 => ip += 4

    float* __restrict__ outp =
        out + (size_t)(b * 64 + c2) * (OUT * OUT) + (size_t)ty * OUT + 12 * q;

    #pragma unroll 4
    for (int it = 0; it < 16; ++it) {
        const float* src = sm + ip * HPP + 4 * q;
        float4 a03 = *reinterpret_cast<const float4*>(src);      // a0..a3
        float2 a45 = *reinterpret_cast<const float2*>(src + 4);  // a4,a5
        float4 v0 = make_float4(a03.x, a03.y, a03.z, a03.y);
        float4 v1 = make_float4(a03.z, a03.w, a03.z, a03.w);
        float4 v2 = make_float4(a45.x, a03.w, a45.x, a45.y);
        reinterpret_cast<float4*>(outp)[0] = v0;
        reinterpret_cast<float4*>(outp)[1] = v1;
        reinterpret_cast<float4*>(outp)[2] = v2;
        outp += (size_t)12 * OUT;
        ip   += 4;
    }
}

extern "C" void kernel_launch(void* const* d_in, const int* in_sizes, int n_in,
                              void* d_out, int out_size) {
    const float* in  = (const float*)d_in[0];
    float*       out = (float*)d_out;
    (void)in_sizes; (void)n_in; (void)out_size;

    dim3 grid(64, BATCH);     // (c2, b)
    padding_jacobians_kernel<<<grid, 192>>>(in, out);
}

// round 5
// speedup vs baseline: 1.8193x; 1.8193x over previous
#include <cuda_runtime.h>
#include <cuda_bf16.h>
#include <cstddef>

// B=32, H=W=64, C=64, K=3, S=1, PAD=1; Hp=Wp=66, OUT=192. Pure gather:
//   out[b,c2,r,s] = up_flat[c2*4356 + ip*66 + jp], ip=r/3+r%3, jp=s/3+s%3
//   up_flat[t]: p=t>>6, c=t&63, rp=p/66, cp=p%66;
//   interior -> in[b, (p-2rp-65), c] else 0.
// Store-side: thread tx writes cols 4tx..4tx+3 (coalesced float4); its 4
// sources lie in src[4j..4j+5], j=tx/3, picked by tx%3:
//   m=0:(a0,a1,a2,a1)  m=1:(a2,a3,a2,a3)  m=2:(a4,a3,a4,a5)
#define HP      66
#define HPP     68               // padded row stride (16B-aligned windows)
#define NP      (HP * HP)        // 4356
#define OUT     192
#define BATCH   32

__global__ __launch_bounds__(192)
void padding_jacobians_kernel(const float* __restrict__ in,
                              float* __restrict__ out) {
    __shared__ float sm[HP * HPP];         // 17952 B

    const unsigned c2 = blockIdx.x;        // 0..63
    const unsigned b  = blockIdx.y;        // 0..31
    const int tx  = threadIdx.x;           // 0..47 (output quad)
    const int ty  = threadIdx.y;           // 0..3
    const int tid = ty * 48 + tx;

    const float* __restrict__ inb = in + (size_t)b * (64 * 64 * 64);
    const unsigned base_t = c2 * NP;       // multiple of 4

    // ---- Load phase: padded 66x66 window into 66x68 smem, float2 granules
    // (t even => c even, never crosses a p boundary). 2178 float2s.
    #pragma unroll 1
    for (unsigned idx = tid; idx < NP / 2; idx += 192) {
        unsigned i   = 2u * idx;                 // window offset (even)
        unsigned row = (i * 993u) >> 16;         // == i/66 (exact, i<4356)
        unsigned col = i - 66u * row;
        unsigned t   = base_t + i;
        unsigned p   = t >> 6;
        unsigned c   = t & 63u;
        unsigned rp  = (p * 993u) >> 16;         // == p/66
        unsigned cp  = p - 66u * rp;
        float2 v = make_float2(0.f, 0.f);
        if ((rp - 1u) < 64u && (cp - 1u) < 64u) {
            v = *reinterpret_cast<const float2*>(inb + ((p - 2u * rp - 65u) << 6) + c);
        }
        *reinterpret_cast<float2*>(sm + row * HPP + col) = v;
    }
    __syncthreads();

    // ---- Store phase: lane tx -> cols 4tx..4tx+3 (coalesced STG.128).
    const int j = tx / 3;                    // 0..15, shared by 3 lanes
    const int m = tx - 3 * j;                // 0,1,2

    float* __restrict__ outp =
        out + (size_t)(b * 64 + c2) * (OUT * OUT) + (size_t)ty * OUT + 4 * tx;

    // ip = r/3 + r%3, r = ty + 4*it; maintain (o=r/3, k=r%3) incrementally
    int o = ty / 3;
    int k = ty % 3;
    #pragma unroll 4
    for (int it = 0; it < OUT / 4; ++it) {
        const float* src = sm + (o + k) * HPP + 4 * j;   // 16B aligned
        float4 a  = *reinterpret_cast<const float4*>(src);      // src[4j..4j+3]
        float2 b2 = *reinterpret_cast<const float2*>(src + 4);  // src[4j+4..5]
        float4 v;
        if (m == 0)      v = make_float4(a.x,  a.y, a.z,  a.y);
        else if (m == 1) v = make_float4(a.z,  a.w, a.z,  a.w);
        else             v = make_float4(b2.x, a.w, b2.x, b2.y);
        *reinterpret_cast<float4*>(outp) = v;
        outp += (size_t)4 * OUT;
        o += (k < 2) ? 1 : 2;                // (r+4)/3
        k = (k == 2) ? 0 : (k + 1);          // (r+4)%3
    }
}

extern "C" void kernel_launch(void* const* d_in, const int* in_sizes, int n_in,
                              void* d_out, int out_size) {
    const float* in  = (const float*)d_in[0];
    float*       out = (float*)d_out;
    (void)in_sizes; (void)n_in; (void)out_size;

    dim3 grid(64, BATCH);     // (c2, b)
    dim3 block(48, 4);        // 192 threads
    padding_jacobians_kernel<<<grid, block>>>(in, out);
}